// round 8
// baseline (speedup 1.0000x reference)
#include <cuda_runtime.h>

// KANModel fused forward, v6: occupancy doubling (SPLIT 16->32).
// R7 insight: duration = instr-count / issue-rate; issue capped at 35% by
// LDS latency with only ~3.5 blocks/SM resident (grid-limited). Double the
// grid to 1024 blocks (~7/SM): same total L2 traffic, 2x latency hiding.

namespace {
constexpr int NBAS  = 8;
constexpr int NC    = 9;                 // silu + 8 bases
constexpr int DIN0  = 128;
constexpr int DOUT0 = 64;
constexpr int BATCH = 1024;
constexpr int TBAT  = 32;                // batches per tile (lane = batch)
constexpr int SPLIT = 32;                // i-chunks
constexpr int ICH   = DIN0 / SPLIT;      // 4
constexpr int BLK   = 256;               // 8 warps; warp handles 8 outputs
constexpr int NTILE = BATCH / TBAT;      // 32
}

__device__ float    g_zpart[SPLIT * DOUT0 * BATCH];  // [s][o][b], 8 MB
__device__ unsigned g_cnt[NTILE];                    // zero-init; reset per pass

// Division-free cubic Cox-de-Boor on uniform knots, u = (x - t0)/h in [0,11).
__device__ __forceinline__ void bspline8u(float u, float* out) {
    float B[11];
#pragma unroll
    for (int j = 0; j < 11; ++j)
        B[j] = (u >= (float)j && u < (float)(j + 1)) ? 1.0f : 0.0f;
#pragma unroll
    for (int j = 0; j < 10; ++j)
        B[j] = (u - (float)j) * B[j] + ((float)(j + 2) - u) * B[j + 1];
#pragma unroll
    for (int j = 0; j < 9; ++j)
        B[j] = 0.5f * ((u - (float)j) * B[j] + ((float)(j + 3) - u) * B[j + 1]);
#pragma unroll
    for (int j = 0; j < 8; ++j)
        out[j] = (1.0f / 3.0f) * ((u - (float)j) * B[j] + ((float)(j + 4) - u) * B[j + 1]);
}

__device__ __forceinline__ float silu_f(float x) {
    return x * (1.0f / (1.0f + __expf(-x)));
}

__global__ __launch_bounds__(BLK) void kan_v6(
    const int*   __restrict__ uidx,  const int*   __restrict__ vidx,
    const float* __restrict__ emb_u, const float* __restrict__ emb_v,
    const float* __restrict__ grid0, const float* __restrict__ coef0,
    const float* __restrict__ sb0,   const float* __restrict__ ssp0,
    const float* __restrict__ bias0,
    const float* __restrict__ grid1, const float* __restrict__ coef1,
    const float* __restrict__ sb1,   const float* __restrict__ ssp1,
    const float* __restrict__ bias1,
    float* __restrict__ out)
{
    __shared__ float  f[ICH * NC * TBAT];        // [i][c][b], b fastest (4.5 KB)
    __shared__ float4 wc[ICH * DOUT0 * 2];       // folded coefs [i][o][2] (8 KB)
    __shared__ float  wb[ICH * DOUT0];           // sb           [i][o]    (1 KB)
    __shared__ float  red[8][TBAT];
    __shared__ int    s_last;

    const int tid  = threadIdx.x;
    const int lane = tid & 31;
    const int w    = tid >> 5;             // warp 0..7
    const int tile = blockIdx.x;           // batch tile 0..31
    const int s    = blockIdx.y;           // i-chunk 0..31
    const int gb   = tile * TBAT + lane;

    // uniform-knot params for layer 0 (all grid rows identical)
    const float g0lo = grid0[0], g0hi = grid0[5];
    const float h0  = (g0hi - g0lo) * 0.2f;
    const float rh0 = 1.0f / h0;
    const float t00 = g0lo - 3.0f * h0;

    // ---- Stage weights: 256 (o,i) pairs, 1 per thread, pre-fold ssp ----
    {
        const float4* c4 = (const float4*)coef0;
        const int o  = tid >> 2;            // 0..63
        const int i  = tid & 3;             // 0..3
        const int n  = o * DIN0 + (s * ICH + i);
        const float sp = ssp0[n];
        float4 ca = c4[2 * n + 0];
        float4 cb = c4[2 * n + 1];
        ca.x *= sp; ca.y *= sp; ca.z *= sp; ca.w *= sp;
        cb.x *= sp; cb.y *= sp; cb.z *= sp; cb.w *= sp;
        wc[(i * DOUT0 + o) * 2 + 0] = ca;
        wc[(i * DOUT0 + o) * 2 + 1] = cb;
        wb[i * DOUT0 + o] = sb0[n];
    }

    // ---- Phase A: 128 features (32 b x 4 i), threads 0..127 ----
    if (tid < ICH * TBAT) {
        const int i  = tid >> 5;           // 0..3
        const int b  = tid & 31;
        const int ii = s * ICH + i;
        const int gbb = tile * TBAT + b;
        float x = (ii < 64) ? emb_u[uidx[gbb] * 64 + ii]
                            : emb_v[vidx[gbb] * 64 + (ii - 64)];
        float Bv[NBAS];
        bspline8u((x - t00) * rh0, Bv);
        f[(i * NC + 0) * TBAT + b] = silu_f(x);
#pragma unroll
        for (int c = 0; c < NBAS; ++c)
            f[(i * NC + 1 + c) * TBAT + b] = Bv[c];
    }
    __syncthreads();

    // ---- Phase B: lane = batch, warp w handles outputs {8w..8w+7} ----
    float acc[8] = {0.f, 0.f, 0.f, 0.f, 0.f, 0.f, 0.f, 0.f};
#pragma unroll
    for (int i = 0; i < ICH; ++i) {
        float fv[NC];
#pragma unroll
        for (int c = 0; c < NC; ++c)
            fv[c] = f[(i * NC + c) * TBAT + lane];  // stride-1, no conflicts
#pragma unroll
        for (int k = 0; k < 8; ++k) {
            const int o = w * 8 + k;                // warp-uniform
            const float4 ca = wc[(i * DOUT0 + o) * 2 + 0];
            const float4 cb = wc[(i * DOUT0 + o) * 2 + 1];
            float a = acc[k];
            a = fmaf(wb[i * DOUT0 + o], fv[0], a);
            a = fmaf(ca.x, fv[1], a);
            a = fmaf(ca.y, fv[2], a);
            a = fmaf(ca.z, fv[3], a);
            a = fmaf(ca.w, fv[4], a);
            a = fmaf(cb.x, fv[5], a);
            a = fmaf(cb.y, fv[6], a);
            a = fmaf(cb.z, fv[7], a);
            a = fmaf(cb.w, fv[8], a);
            acc[k] = a;
        }
    }
#pragma unroll
    for (int k = 0; k < 8; ++k)
        g_zpart[(s * DOUT0 + (w * 8 + k)) * BATCH + gb] = acc[k];

    // ---- publish + elect last block of this tile ----
    __threadfence();
    __syncthreads();
    if (tid == 0) {
        unsigned old = atomicAdd(&g_cnt[tile], 1u);
        s_last = (old == SPLIT - 1) ? 1 : 0;
    }
    __syncthreads();
    if (!s_last) return;
    __threadfence();

    // ---- Epilogue (last block of tile): reduce + bias0 + layer 1 + sigmoid ----
    {
        const float g1lo = grid1[0], g1hi = grid1[5];
        const float h1  = (g1hi - g1lo) * 0.2f;
        const float rh1 = 1.0f / h1;
        const float t10 = g1lo - 3.0f * h1;

        const float4* c4 = (const float4*)coef1;
        float part = 0.f;
#pragma unroll 2
        for (int k = 0; k < 8; ++k) {
            const int o = w * 8 + k;
            float zb = bias0[o];
#pragma unroll
            for (int ss = 0; ss < SPLIT; ++ss)
                zb += g_zpart[(ss * DOUT0 + o) * BATCH + gb];  // coalesced
            float Bv[NBAS];
            bspline8u((zb - t10) * rh1, Bv);
            float4 ca = c4[2 * o + 0];
            float4 cb = c4[2 * o + 1];
            float d = ca.x * Bv[0];
            d = fmaf(ca.y, Bv[1], d);
            d = fmaf(ca.z, Bv[2], d);
            d = fmaf(ca.w, Bv[3], d);
            d = fmaf(cb.x, Bv[4], d);
            d = fmaf(cb.y, Bv[5], d);
            d = fmaf(cb.z, Bv[6], d);
            d = fmaf(cb.w, Bv[7], d);
            part += sb1[o] * silu_f(zb) + ssp1[o] * d;
        }
        red[w][lane] = part;
        __syncthreads();
        if (w == 0) {
            float y = bias1[0];
#pragma unroll
            for (int g = 0; g < 8; ++g) y += red[g][lane];
            out[gb] = 1.0f / (1.0f + __expf(-y));
        }
        if (tid == 0) g_cnt[tile] = 0;   // reset for next graph replay
    }
}

extern "C" void kernel_launch(void* const* d_in, const int* in_sizes, int n_in,
                              void* d_out, int out_size) {
    // Layout (16 inputs): 0:uidx 1:vidx 2:gun 3:sgus 4:emb_u 5:emb_v
    //   6:grid0 7:coef0 8:sb0 9:ssp0 10:bias0 11:grid1 12:coef1 13:sb1
    //   14:ssp1 15:bias1.  Robust to scalar materialization.
    const int s = (n_in >= 16) ? 2 : (n_in - 14);
    const int*   uidx  = (const int*)  d_in[0];
    const int*   vidx  = (const int*)  d_in[1];
    const float* embu  = (const float*)d_in[2 + s];
    const float* embv  = (const float*)d_in[3 + s];
    const float* grid0 = (const float*)d_in[4 + s];
    const float* coef0 = (const float*)d_in[5 + s];
    const float* sb0   = (const float*)d_in[6 + s];
    const float* ssp0  = (const float*)d_in[7 + s];
    const float* bias0 = (const float*)d_in[8 + s];
    const float* grid1 = (const float*)d_in[9 + s];
    const float* coef1 = (const float*)d_in[10 + s];
    const float* sb1   = (const float*)d_in[11 + s];
    const float* ssp1  = (const float*)d_in[12 + s];
    const float* bias1 = (const float*)d_in[13 + s];
    float* outp = (float*)d_out;

    dim3 g(NTILE, SPLIT);   // 32 x 32 = 1024 blocks
    kan_v6<<<g, BLK>>>(uidx, vidx, embu, embv,
                       grid0, coef0, sb0, ssp0, bias0,
                       grid1, coef1, sb1, ssp1, bias1, outp);
}